// round 8
// baseline (speedup 1.0000x reference)
#include <cuda_runtime.h>

// Conv2D 4096x4096 fp32 * 16x16, VALID -> 4081x4081, + bias.
// Packed f32x2 (FFMA2) kernel: 2 vertically-adjacent outputs per 64-bit acc.

#define H  4096
#define W  4096
#define KH 16
#define KW 16
#define OH 4081
#define OW 4081

#define BW    128        // output cols per block (1 col per thread)
#define BH    32         // output rows per block (all in one thread)
#define NP    16         // packed accumulators per thread (= BH/2)
#define INR   47         // input rows per tile (BH + KH - 1)
#define RP    50         // smem row-pitch per column (floats): 200B stride, even (8B-align), bank-clean
#define NCOLS 143        // input cols per tile (BW + KW - 1)

typedef unsigned long long u64;

__device__ __forceinline__ void ffma2(u64 &d, u64 a, u64 b) {
    asm("fma.rn.f32x2 %0, %1, %2, %0;" : "+l"(d) : "l"(a), "l"(b));
}
__device__ __forceinline__ u64 pack2(float lo, float hi) {
    u64 r; asm("mov.b64 %0, {%1, %2};" : "=l"(r) : "f"(lo), "f"(hi)); return r;
}
__device__ __forceinline__ void unpack2(u64 v, float &lo, float &hi) {
    asm("mov.b64 {%0, %1}, %2;" : "=f"(lo), "=f"(hi) : "l"(v));
}

__global__ __launch_bounds__(128, 3)
void Conv2D_87058987090635_kernel(const float* __restrict__ x,
                                  const float* __restrict__ w,
                                  const float* __restrict__ bias,
                                  float* __restrict__ out)
{
    __shared__ __align__(16) float xsT[NCOLS * RP];  // column-major tile: 28.6 KB
    __shared__ u64 wsp[KW * KH];                     // splatted weights {w,w}: 2 KB

    const int tid = threadIdx.x;                     // 0..127 -> output col in tile
    const int gc0 = blockIdx.x * BW;
    const int gr0 = blockIdx.y * BH;

    // --- splat weight table: wsp[b*16 + a] = {w[a][b], w[a][b]} ---
    #pragma unroll
    for (int i = tid; i < KH * KW; i += 128) {
        const int b = i >> 4, a = i & 15;
        const float wv = w[a * KW + b];
        wsp[i] = pack2(wv, wv);
    }

    // --- fill transposed tile: xsT[c*RP + k] = x[gr0+k][gc0+c] ---
    for (int s = tid; s < NCOLS * INR; s += 128) {
        const int k = s / NCOLS;            // input row within tile
        const int c = s - k * NCOLS;        // input col within tile (fastest -> coalesced LDG)
        const int gr = gr0 + k, gc = gc0 + c;
        float v = 0.f;
        if (gr < H && gc < W) v = x[(size_t)gr * W + gc];
        xsT[c * RP + k] = v;
    }
    __syncthreads();

    const float b0 = bias[0];
    u64 acc[NP];
    #pragma unroll
    for (int p = 0; p < NP; ++p) acc[p] = pack2(b0, b0);

    #pragma unroll 1
    for (int b = 0; b < KW; ++b) {
        const float* colp = &xsT[(tid + b) * RP];

        // even-aligned vertical pairs E[m] = {c[2m], c[2m+1]}, m=0..22
        u64 E[23];
        #pragma unroll
        for (int m = 0; m < 23; ++m)
            E[m] = *reinterpret_cast<const u64*>(colp + 2 * m);
        const float c46 = colp[46];

        // odd-aligned pairs O[m] = {c[2m+1], c[2m+2]}, m=0..22 (register-built)
        u64 O[23];
        {
            float lo, hi, prevH;
            unpack2(E[0], lo, prevH);
            #pragma unroll
            for (int m = 1; m < 23; ++m) {
                unpack2(E[m], lo, hi);
                O[m - 1] = pack2(prevH, lo);
                prevH = hi;
            }
            O[22] = pack2(prevH, c46);
        }

        const u64* wb = &wsp[b * KH];
        #pragma unroll
        for (int a = 0; a < KH; ++a) {
            const u64 wp = wb[a];           // broadcast LDS.64
            #pragma unroll
            for (int p = 0; p < NP; ++p) {
                const int k = a + 2 * p;    // compile-time
                const u64 src = (k & 1) ? O[(k - 1) >> 1] : E[k >> 1];
                ffma2(acc[p], wp, src);
            }
        }
    }

    // --- epilogue: unpack and store ---
    const int ocol = gc0 + tid;
    if (ocol < OW) {
        #pragma unroll
        for (int p = 0; p < NP; ++p) {
            float lo, hi;
            unpack2(acc[p], lo, hi);
            const int r0 = gr0 + 2 * p;
            if (r0 < OH)     out[(size_t)r0 * OW + ocol]       = lo;
            if (r0 + 1 < OH) out[(size_t)(r0 + 1) * OW + ocol] = hi;
        }
    }
}

extern "C" void kernel_launch(void* const* d_in, const int* in_sizes, int n_in,
                              void* d_out, int out_size)
{
    const float* x    = (const float*)d_in[0];
    const float* w    = (const float*)d_in[1];
    const float* bias = (const float*)d_in[2];
    float* out        = (float*)d_out;

    dim3 block(128);
    dim3 grid((OW + BW - 1) / BW,   // 32
              (OH + BH - 1) / BH);  // 128
    Conv2D_87058987090635_kernel<<<grid, block>>>(x, w, bias, out);
}

// round 9
// speedup vs baseline: 1.1509x; 1.1509x over previous
#include <cuda_runtime.h>

// Conv2D 4096x4096 fp32 * 16x16, VALID -> 4081x4081, + bias.
// FFMA2 (fma.rn.f32x2) with dual accumulator sets (even/odd filter-row parity),
// so every input pair is a direct aligned LDS.64 — no register packing ALU.

#define H  4096
#define W  4096
#define KH 16
#define KW 16
#define OH 4081
#define OW 4081

#define BW    128        // output cols per block (1 col per thread)
#define BH    24         // output rows per block (all in one thread)
#define NA    12         // accA count (= BH/2)
#define NB    12         // accB count (last one has a pad hi-half)
#define INR   40         // input rows per tile (max float index 39)
#define RP    42         // smem column pitch (floats): even, 168B stride, conflict-free
#define NCOLS 143        // input cols per tile (BW + KW - 1)
#define NE    20         // even pairs per column window

typedef unsigned long long u64;

__device__ __forceinline__ void ffma2(u64 &d, u64 a, u64 b) {
    asm("fma.rn.f32x2 %0, %1, %2, %0;" : "+l"(d) : "l"(a), "l"(b));
}
__device__ __forceinline__ u64 pack2(float lo, float hi) {
    u64 r; asm("mov.b64 %0, {%1, %2};" : "=l"(r) : "f"(lo), "f"(hi)); return r;
}
__device__ __forceinline__ void unpack2(u64 v, float &lo, float &hi) {
    asm("mov.b64 {%0, %1}, %2;" : "=f"(lo), "=f"(hi) : "l"(v));
}
__device__ __forceinline__ float lo_f(u64 v) {
    return __int_as_float((int)(unsigned)v);
}
__device__ __forceinline__ float hi_f(u64 v) {
    return __int_as_float((int)(v >> 32));
}

__global__ __launch_bounds__(128, 4)
void Conv2D_87058987090635_kernel(const float* __restrict__ x,
                                  const float* __restrict__ w,
                                  const float* __restrict__ bias,
                                  float* __restrict__ out)
{
    __shared__ __align__(16) float xsT[NCOLS * RP];  // 143*42*4 = 24 KB, column-major
    __shared__ u64 wsp[KW * KH];                     // splatted weights {w,w}: 2 KB

    const int tid = threadIdx.x;                     // 0..127 -> output col in tile
    const int gc0 = blockIdx.x * BW;
    const int gr0 = blockIdx.y * BH;

    // --- splat weight table: wsp[b*16 + a] = {w[a][b], w[a][b]} ---
    #pragma unroll
    for (int i = tid; i < KH * KW; i += 128) {
        const int b = i >> 4, a = i & 15;
        const float wv = w[a * KW + b];
        wsp[i] = pack2(wv, wv);
    }

    // --- fill transposed tile: xsT[c*RP + k] = x[gr0+k][gc0+c], zero OOB ---
    for (int s = tid; s < NCOLS * INR; s += 128) {
        const int k = s / NCOLS;            // input row within tile
        const int c = s - k * NCOLS;        // input col within tile (fastest -> coalesced LDG)
        const int gr = gr0 + k, gc = gc0 + c;
        float v = 0.f;
        if (gr < H && gc < W) v = x[(size_t)gr * W + gc];
        xsT[c * RP + k] = v;
    }
    __syncthreads();

    u64 accA[NA];                           // {y[2p], y[2p+1]} : even-a contributions
    u64 accB[NB];                           // {y[2q+1], y[2q+2]} : odd-a contributions (B[11].hi = pad)
    float y0odd = 0.f;                      // y[0], odd-a contributions
    #pragma unroll
    for (int p = 0; p < NA; ++p) accA[p] = 0ull;
    #pragma unroll
    for (int q = 0; q < NB; ++q) accB[q] = 0ull;

    #pragma unroll 1
    for (int b = 0; b < KW; ++b) {
        const float* colp = &xsT[(tid + b) * RP];

        // even-aligned vertical pairs E[m] = {col[2m], col[2m+1]}
        u64 E[NE];
        #pragma unroll
        for (int m = 0; m < NE; ++m)
            E[m] = *reinterpret_cast<const u64*>(colp + 2 * m);

        const u64* wb = &wsp[b * KH];
        #pragma unroll
        for (int a = 0; a < KH; ++a) {
            const u64 wp = wb[a];           // broadcast LDS.64
            if ((a & 1) == 0) {
                // pair index (2p+a)/2 = p + a/2  (even -> direct E)
                #pragma unroll
                for (int p = 0; p < NA; ++p)
                    ffma2(accA[p], wp, E[p + (a >> 1)]);
            } else {
                // pair index (2q+1+a)/2 = q + (a+1)/2  (even -> direct E)
                #pragma unroll
                for (int q = 0; q < NB; ++q)
                    ffma2(accB[q], wp, E[q + ((a + 1) >> 1)]);
                // y[0] += w[a] * col[a]  (col[a] = hi half of E[(a-1)/2])
                y0odd = fmaf(hi_f(E[(a - 1) >> 1]), lo_f(wp), y0odd);
            }
        }
    }

    // --- epilogue: recombine parities, add bias, store ---
    const float b0 = bias[0];
    const int ocol = gc0 + tid;
    if (ocol < OW) {
        float yA_lo[NA], yA_hi[NA], yB_lo[NB], yB_hi[NB];
        #pragma unroll
        for (int p = 0; p < NA; ++p) unpack2(accA[p], yA_lo[p], yA_hi[p]);
        #pragma unroll
        for (int q = 0; q < NB; ++q) unpack2(accB[q], yB_lo[q], yB_hi[q]);

        float y[BH];
        y[0] = yA_lo[0] + y0odd;
        #pragma unroll
        for (int p = 0; p < NA; ++p)        // odd rows 2p+1
            y[2 * p + 1] = yA_hi[p] + yB_lo[p];
        #pragma unroll
        for (int p = 1; p < NA; ++p)        // even rows 2p
            y[2 * p] = yA_lo[p] + yB_hi[p - 1];

        #pragma unroll
        for (int r = 0; r < BH; ++r) {
            const int orow = gr0 + r;
            if (orow < OH)
                out[(size_t)orow * OW + ocol] = y[r] + b0;
        }
    }
}

extern "C" void kernel_launch(void* const* d_in, const int* in_sizes, int n_in,
                              void* d_out, int out_size)
{
    const float* x    = (const float*)d_in[0];
    const float* w    = (const float*)d_in[1];
    const float* bias = (const float*)d_in[2];
    float* out        = (float*)d_out;

    dim3 block(128);
    dim3 grid((OW + BW - 1) / BW,    // 32
              (OH + BH - 1) / BH);   // 171
    Conv2D_87058987090635_kernel<<<grid, block>>>(x, w, bias, out);
}

// round 12
// speedup vs baseline: 1.1780x; 1.0236x over previous
#include <cuda_runtime.h>

// Conv2D 4096x4096 fp32 * 16x16, VALID -> 4081x4081, + bias.
// Scalar-FFMA kernel (FFMA = 1/cyc/SMSP on sm_103a; f32x2 gives no pipe gain).
// Column-major smem tile so each thread's vertical window loads as LDS.128.
// (Resubmission of R9 design — previous bench died to container infra failure.)

#define H  4096
#define W  4096
#define KH 16
#define KW 16
#define OH 4081
#define OW 4081

#define BW    128        // output cols per block (1 col per thread-x)
#define BH    32         // output rows per block (2 row-groups of 16)
#define TR    16         // output rows per thread
#define INR   47         // input rows per tile (BH + KH - 1)
#define RP    52         // column pitch (floats): 208B lane stride, mult-of-4 (16B align),
                         // 20*l mod 32 distinct over 8-lane phases -> conflict-free LDS.128
#define NCOLS 143        // input cols per tile (BW + KW - 1)

__global__ __launch_bounds__(256, 4)
void Conv2D_87058987090635_kernel(const float* __restrict__ x,
                                  const float* __restrict__ w,
                                  const float* __restrict__ bias,
                                  float* __restrict__ out)
{
    __shared__ __align__(16) float xsT[NCOLS * RP];  // 143*52*4 = 29.7 KB, column-major
    __shared__ float ws[KW * KH];                    // weights, b-major: ws[b*16+a] = w[a][b]

    const int tx  = threadIdx.x;            // 0..127 -> output col within tile
    const int ty  = threadIdx.y;            // 0..1   -> row-group
    const int tid = ty * 128 + tx;

    const int gc0 = blockIdx.x * BW;
    const int gr0 = blockIdx.y * BH;

    // --- bias early (LDG latency hides under the fill + barrier) ---
    const float b0 = bias[0];

    // --- weights to smem, transposed to b-major ---
    ws[tid & 255] = w[(tid & 15) * KW + (tid >> 4)];

    // --- fill transposed tile: xsT[c*RP + k] = x[gr0+k][gc0+c] (c fastest -> coalesced LDG) ---
    for (int s = tid; s < NCOLS * INR; s += 256) {
        const int k = s / NCOLS;
        const int c = s - k * NCOLS;
        const int gr = gr0 + k, gc = gc0 + c;
        float v = 0.f;
        if (gr < H && gc < W) v = x[(size_t)gr * W + gc];
        xsT[c * RP + k] = v;
    }
    __syncthreads();

    const int ry0 = ty * TR;

    float acc[TR];
    #pragma unroll
    for (int r = 0; r < TR; ++r) acc[r] = 0.f;

    #pragma unroll 1
    for (int b = 0; b < KW; ++b) {
        // vertical window col[0..31] = rows ry0..ry0+31 of input column (tx+b): 8x LDS.128
        const float4* cp = reinterpret_cast<const float4*>(&xsT[(tx + b) * RP + ry0]);
        float col[TR + KH];
        #pragma unroll
        for (int m = 0; m < 8; ++m) {
            const float4 v = cp[m];
            col[4 * m + 0] = v.x;
            col[4 * m + 1] = v.y;
            col[4 * m + 2] = v.z;
            col[4 * m + 3] = v.w;
        }

        const float* wb = &ws[b * KH];
        #pragma unroll
        for (int a = 0; a < KH; ++a) {
            const float wv = wb[a];         // broadcast LDS.32
            #pragma unroll
            for (int r = 0; r < TR; ++r)
                acc[r] = fmaf(col[a + r], wv, acc[r]);
        }
    }

    // --- epilogue ---
    const int ocol = gc0 + tx;
    if (ocol < OW) {
        #pragma unroll
        for (int r = 0; r < TR; ++r) {
            const int orow = gr0 + ry0 + r;
            if (orow < OH)
                out[(size_t)orow * OW + ocol] = acc[r] + b0;
        }
    }
}

extern "C" void kernel_launch(void* const* d_in, const int* in_sizes, int n_in,
                              void* d_out, int out_size)
{
    const float* x    = (const float*)d_in[0];
    const float* w    = (const float*)d_in[1];
    const float* bias = (const float*)d_in[2];
    float* out        = (float*)d_out;

    dim3 block(128, 2);
    dim3 grid((OW + BW - 1) / BW,    // 32
              (OH + BH - 1) / BH);   // 128
    Conv2D_87058987090635_kernel<<<grid, block>>>(x, w, bias, out);
}

// round 15
// speedup vs baseline: 1.5214x; 1.2915x over previous
#include <cuda_runtime.h>
#include <cuda_bf16.h>

// Conv2D 4096x4096 fp32 * 16x16 -> 4081x4081 (+bias) via mma.sync (HMMA) bf16
// 3-pass split Toeplitz GEMM. y[m,u] = sum_{a,c} x[m+a, c] * w[a, c-u].
// Key identity: with u-group shift == c-window shift, B[k,n] = w[a, k-n]
// (k16) and w[a, 16+k-n] (k8) independent of the u-group -> tiny B table.

typedef unsigned int u32;

#define H  4096
#define W  4096
#define OH 4081
#define OW 4081

#define TM 256               // output rows per CTA (8 warps x 32)
#define TN 16                // output cols per CTA
#define AR 271               // input rows per tile (TM + 15)
#define AP 80                // A row pitch (bytes): 32 bf16 data + pad; LDSM conflict-free
#define ASPLIT (AR * AP)     // 21680 bytes per split
#define OFF_B  (2 * ASPLIT)  // 43360
#define SMEM_TOTAL (OFF_B + 12288)   // 55648

__device__ __forceinline__ u32 smem_u32(const void* p) {
    u32 a;
    asm("{ .reg .u64 t; cvta.to.shared.u64 t, %1; cvt.u32.u64 %0, t; }"
        : "=r"(a) : "l"(p));
    return a;
}
__device__ __forceinline__ u32 bf2(float a, float b) {
    const u32 lo = (u32)__bfloat16_as_ushort(__float2bfloat16(a));
    const u32 hi = (u32)__bfloat16_as_ushort(__float2bfloat16(b));
    return (hi << 16) | lo;
}
__device__ __forceinline__ float rs(float v) {      // bf16 residual
    return v - __bfloat162float(__float2bfloat16(v));
}
__device__ __forceinline__ void ldmx4(u32* r, u32 addr) {
    asm volatile("ldmatrix.sync.aligned.m8n8.x4.shared.b16 {%0,%1,%2,%3}, [%4];"
                 : "=r"(r[0]), "=r"(r[1]), "=r"(r[2]), "=r"(r[3]) : "r"(addr));
}
__device__ __forceinline__ void ldmx2(u32* r, u32 addr) {
    asm volatile("ldmatrix.sync.aligned.m8n8.x2.shared.b16 {%0,%1}, [%2];"
                 : "=r"(r[0]), "=r"(r[1]) : "r"(addr));
}
__device__ __forceinline__ void mma16(float* d, const u32* a, u32 b0, u32 b1) {
    asm volatile("mma.sync.aligned.m16n8k16.row.col.f32.bf16.bf16.f32 "
                 "{%0,%1,%2,%3}, {%4,%5,%6,%7}, {%8,%9}, {%0,%1,%2,%3};"
                 : "+f"(d[0]), "+f"(d[1]), "+f"(d[2]), "+f"(d[3])
                 : "r"(a[0]), "r"(a[1]), "r"(a[2]), "r"(a[3]), "r"(b0), "r"(b1));
}
__device__ __forceinline__ void mma8(float* d, u32 a0, u32 a1, u32 b0) {
    asm volatile("mma.sync.aligned.m16n8k8.row.col.f32.bf16.bf16.f32 "
                 "{%0,%1,%2,%3}, {%4,%5}, {%6}, {%0,%1,%2,%3};"
                 : "+f"(d[0]), "+f"(d[1]), "+f"(d[2]), "+f"(d[3])
                 : "r"(a0), "r"(a1), "r"(b0));
}

__global__ __launch_bounds__(256, 2)
void Conv2D_87058987090635_kernel(const float* __restrict__ x,
                                  const float* __restrict__ w,
                                  const float* __restrict__ bias,
                                  float* __restrict__ out)
{
    extern __shared__ __align__(16) char smem[];
    const int tid = threadIdx.x, lane = tid & 31, wg = tid >> 5;
    const int j0 = blockIdx.x * TN;
    const int i0 = blockIdx.y * TM;
    const float b0 = bias[0];
    u32* Bt = (u32*)(smem + OFF_B);

    // --- B fragment table: Bt[((sp*16+a)*3+reg)*32 + lane] ---
    // reg0/1: k16 frag (b0: k=2(ln%4)+{0,1}; b1: +8), val = w_sp[a][k-n]
    // reg2  : k8  frag,                          val = w_sp[a][16+k-n]
    for (int s = tid; s < 3072; s += 256) {
        const int ln = s & 31, t = s >> 5;
        const int reg = t % 3, a = (t / 3) & 15, sp = t / 48;
        const int n = ln >> 2, kb = 2 * (ln & 3);
        u32 v = 0;
        #pragma unroll
        for (int e = 0; e < 2; ++e) {
            const int k = kb + e + (reg == 1 ? 8 : 0);
            const int d = (reg == 2) ? (16 + k - n) : (k - n);
            float f = 0.f;
            if (d >= 0 && d < 16) {
                const float wv = w[a * 16 + d];
                const float wh = __bfloat162float(__float2bfloat16(wv));
                f = sp ? (wv - wh) : wh;
            }
            v |= (u32)__bfloat16_as_ushort(__float2bfloat16(f)) << (16 * e);
        }
        Bt[s] = v;
    }

    // --- A tile fill: 271 rows x 32 cols, bf16 hi + lo splits ---
    for (int s = tid; s < AR * 8; s += 256) {
        const int r = s >> 3, c4 = s & 7;
        const int gr = i0 + r, gc = j0 + c4 * 4;
        float4 v = make_float4(0.f, 0.f, 0.f, 0.f);
        if (gr < H && gc < W)                       // gc,W mult of 4 -> all-or-none
            v = *(const float4*)(x + (size_t)gr * W + gc);
        char* ap = smem + r * AP + c4 * 8;
        *(u32*)(ap)              = bf2(v.x, v.y);
        *(u32*)(ap + 4)          = bf2(v.z, v.w);
        *(u32*)(ap + ASPLIT)     = bf2(rs(v.x), rs(v.y));
        *(u32*)(ap + ASPLIT + 4) = bf2(rs(v.z), rs(v.w));
    }
    __syncthreads();

    // --- mainloop: all accumulation in registers ---
    float D[2][2][4];
    #pragma unroll
    for (int h = 0; h < 2; ++h)
        #pragma unroll
        for (int g = 0; g < 2; ++g)
            #pragma unroll
            for (int i = 0; i < 4; ++i) D[h][g][i] = 0.f;

    const u32 sb = smem_u32(smem);
    u32 arow = sb + (u32)((32 * wg + (lane & 15)) * AP);   // hi split, per-lane row base
    const u32 koff = ((u32)(lane >> 4)) << 4;              // k-half offset for x4

    #pragma unroll 1
    for (int a = 0; a < 16; ++a) {
        const u32 Bh0 = Bt[(a * 3 + 0) * 32 + lane];
        const u32 Bh1 = Bt[(a * 3 + 1) * 32 + lane];
        const u32 Bh2 = Bt[(a * 3 + 2) * 32 + lane];
        const u32 Bl0 = Bt[1536 + (a * 3 + 0) * 32 + lane];
        const u32 Bl1 = Bt[1536 + (a * 3 + 1) * 32 + lane];
        const u32 Bl2 = Bt[1536 + (a * 3 + 2) * 32 + lane];

        u32 A0[4], A1[4], A2[2];
        #pragma unroll
        for (int h = 0; h < 2; ++h) {               // hi split: passes hh + hl
            const u32 base = arow + (u32)(h * 16 * AP);
            ldmx4(A0, base + koff);                 // c in [0,16)
            ldmx4(A1, base + 16 + koff);            // c in [8,24); regs23 = c [16,24)
            ldmx2(A2, base + 48);                   // c in [24,32)
            mma16(D[h][0], A0, Bh0, Bh1);
            mma8 (D[h][0], A1[2], A1[3], Bh2);
            mma16(D[h][1], A1, Bh0, Bh1);
            mma8 (D[h][1], A2[0], A2[1], Bh2);
            mma16(D[h][0], A0, Bl0, Bl1);
            mma8 (D[h][0], A1[2], A1[3], Bl2);
            mma16(D[h][1], A1, Bl0, Bl1);
            mma8 (D[h][1], A2[0], A2[1], Bl2);
        }
        #pragma unroll
        for (int h = 0; h < 2; ++h) {               // lo split: pass lh
            const u32 base = arow + ASPLIT + (u32)(h * 16 * AP);
            ldmx4(A0, base + koff);
            ldmx4(A1, base + 16 + koff);
            ldmx2(A2, base + 48);
            mma16(D[h][0], A0, Bh0, Bh1);
            mma8 (D[h][0], A1[2], A1[3], Bh2);
            mma16(D[h][1], A1, Bh0, Bh1);
            mma8 (D[h][1], A2[0], A2[1], Bh2);
        }
        arow += AP;
    }

    // --- epilogue: D frag -> gmem (+bias), guarded ---
    const int rbase = i0 + 32 * wg + (lane >> 2);
    const int cbase = j0 + 2 * (lane & 3);
    #pragma unroll
    for (int h = 0; h < 2; ++h) {
        #pragma unroll
        for (int g = 0; g < 2; ++g) {
            const float* dd = D[h][g];
            const int cc = cbase + 8 * g;
            #pragma unroll
            for (int rr = 0; rr < 2; ++rr) {
                const int orow = rbase + 16 * h + 8 * rr;
                if (orow < OH) {
                    if (cc < OW)     out[(size_t)orow * OW + cc]     = dd[2 * rr]     + b0;
                    if (cc + 1 < OW) out[(size_t)orow * OW + cc + 1] = dd[2 * rr + 1] + b0;
                }
            }
        }
    }
}

extern "C" void kernel_launch(void* const* d_in, const int* in_sizes, int n_in,
                              void* d_out, int out_size)
{
    const float* x    = (const float*)d_in[0];
    const float* w    = (const float*)d_in[1];
    const float* bias = (const float*)d_in[2];
    float* out        = (float*)d_out;

    cudaFuncSetAttribute(Conv2D_87058987090635_kernel,
                         cudaFuncAttributeMaxDynamicSharedMemorySize, SMEM_TOTAL);

    dim3 grid(256, 16);     // 256 j-tiles x 16 i-tiles
    Conv2D_87058987090635_kernel<<<grid, 256, SMEM_TOTAL>>>(x, w, bias, out);
}